// round 13
// baseline (speedup 1.0000x reference)
#include <cuda_runtime.h>
#include <cuda_bf16.h>
#include <stdint.h>

// Problem constants
#define PB 4
#define PS 2048
#define PD 1024
#define PH 16
#define PHD 64
#define M_ROWS 8192
#define QKV_N 3072

typedef __nv_bfloat16 bf16;

// Scratch (allocation-free: __device__ globals)
__device__ bf16 g_xhi[M_ROWS * PD];
__device__ bf16 g_xlo[M_ROWS * PD];
__device__ bf16 g_wqT_hi[QKV_N * PD];          // W_qkv^T  [N=3072][K=1024]
__device__ bf16 g_wqT_lo[QKV_N * PD];
__device__ bf16 g_woT_hi[PD * PD];             // W_out^T  [N=1024][K=1024]
__device__ bf16 g_woT_lo[PD * PD];
__device__ bf16 g_qhi[M_ROWS * PD];            // Q [B,H,S,HD]
__device__ bf16 g_qlo[M_ROWS * PD];
__device__ bf16 g_khi[M_ROWS * PD];            // K [B,H,S,HD]
__device__ bf16 g_klo[M_ROWS * PD];
__device__ bf16 g_vhi[M_ROWS * PD];            // V [B,H,S,HD]
__device__ bf16 g_vlo[M_ROWS * PD];
__device__ bf16 g_ahi[M_ROWS * PD];            // attention out (merged heads)
__device__ bf16 g_alo[M_ROWS * PD];

// ---------------------------------------------------------------------------
// Base-ISA helpers only (sm_80-level: guaranteed to compile at sm_103)
// ---------------------------------------------------------------------------
__device__ __forceinline__ uint32_t smem_u32(const void* p) {
    return (uint32_t)__cvta_generic_to_shared(p);
}
__device__ __forceinline__ void cp16(uint32_t dst, const void* src) {
    asm volatile("cp.async.cg.shared.global [%0], [%1], 16;" :: "r"(dst), "l"(src));
}
__device__ __forceinline__ void cp_commit() { asm volatile("cp.async.commit_group;"); }
template <int N>
__device__ __forceinline__ void cp_wait() { asm volatile("cp.async.wait_group %0;" :: "n"(N)); }

__device__ __forceinline__ void ldsm_x4(uint32_t r[4], uint32_t addr) {
    asm volatile("ldmatrix.sync.aligned.m8n8.x4.shared.b16 {%0,%1,%2,%3}, [%4];"
                 : "=r"(r[0]), "=r"(r[1]), "=r"(r[2]), "=r"(r[3]) : "r"(addr));
}
__device__ __forceinline__ void ldsm_x4_t(uint32_t r[4], uint32_t addr) {
    asm volatile("ldmatrix.sync.aligned.m8n8.x4.trans.shared.b16 {%0,%1,%2,%3}, [%4];"
                 : "=r"(r[0]), "=r"(r[1]), "=r"(r[2]), "=r"(r[3]) : "r"(addr));
}
__device__ __forceinline__ void mma_bf16(float* c, const uint32_t* a, const uint32_t* b) {
    asm volatile(
        "mma.sync.aligned.m16n8k16.row.col.f32.bf16.bf16.f32 "
        "{%0,%1,%2,%3}, {%4,%5,%6,%7}, {%8,%9}, {%0,%1,%2,%3};"
        : "+f"(c[0]), "+f"(c[1]), "+f"(c[2]), "+f"(c[3])
        : "r"(a[0]), "r"(a[1]), "r"(a[2]), "r"(a[3]), "r"(b[0]), "r"(b[1]));
}
// split (f0,f1) into packed bf16 hi pair (returned) and lo pair (out param)
__device__ __forceinline__ uint32_t split_pack(float f0, float f1, uint32_t& lo) {
    __nv_bfloat16 h0 = __float2bfloat16(f0), h1 = __float2bfloat16(f1);
    __nv_bfloat162 hp; hp.x = h0; hp.y = h1;
    __nv_bfloat162 lp;
    lp.x = __float2bfloat16(f0 - __bfloat162float(h0));
    lp.y = __float2bfloat16(f1 - __bfloat162float(h1));
    lo = *(uint32_t*)&lp;
    return *(uint32_t*)&hp;
}

// ---------------------------------------------------------------------------
// Pre-pass: split x (fp32) into bf16 hi/lo
// ---------------------------------------------------------------------------
__global__ void convert_x_kernel(const float* __restrict__ x,
                                 bf16* __restrict__ hi, bf16* __restrict__ lo, int n4)
{
    int i = blockIdx.x * blockDim.x + threadIdx.x;
    if (i >= n4) return;
    float4 v = ((const float4*)x)[i];
    uint32_t l0, l1;
    uint32_t h0 = split_pack(v.x, v.y, l0);
    uint32_t h1 = split_pack(v.z, v.w, l1);
    *(uint32_t*)&hi[i * 4]     = h0;
    *(uint32_t*)&hi[i * 4 + 2] = h1;
    *(uint32_t*)&lo[i * 4]     = l0;
    *(uint32_t*)&lo[i * 4 + 2] = l1;
}

// ---------------------------------------------------------------------------
// Pre-pass: transpose W[K,N] fp32 -> T[N,K] bf16 hi/lo
// ---------------------------------------------------------------------------
__global__ void transpose_split_kernel(const float* __restrict__ W,
                                       bf16* __restrict__ Thi, bf16* __restrict__ Tlo,
                                       int K, int N)
{
    __shared__ float t[32][33];
    const int tx = threadIdx.x, ty = threadIdx.y;
    const int n = blockIdx.x * 32 + tx;
#pragma unroll
    for (int j = 0; j < 4; j++) {
        int k = blockIdx.y * 32 + ty + j * 8;
        t[ty + j * 8][tx] = W[(size_t)k * N + n];
    }
    __syncthreads();
    const int k = blockIdx.y * 32 + tx;
#pragma unroll
    for (int j = 0; j < 4; j++) {
        int n2 = blockIdx.x * 32 + ty + j * 8;
        float v = t[tx][ty + j * 8];
        __nv_bfloat16 h = __float2bfloat16(v);
        Thi[(size_t)n2 * K + k] = h;
        Tlo[(size_t)n2 * K + k] = __float2bfloat16(v - __bfloat162float(h));
    }
}

// ---------------------------------------------------------------------------
// Split-bf16 GEMM via mma.sync: C[M,N] = A[M,K] @ B[N,K]^T + bias
// CTA 128x128, 8 warps (warp tile 32x64), k-chunk 64 (BK=64), cp.async
// THREE-stage ring (cp_wait<1>: 2 stages in flight), ONE barrier per stage.
// 144B smem rows -> conflict-free ldmatrix.
// MODE 0: fp32 write (out-projection). MODE 1: fused split-bf16 scatter.
// ---------------------------------------------------------------------------
#define GS_A_HI  0
#define GS_A_LO  18432
#define GS_B_HI  36864
#define GS_B_LO  55296
#define GS_STAGE 73728
#define GEMM_SMEM (3 * GS_STAGE)     // 221184 <= 227KB dynamic limit

__device__ __forceinline__ void gemm_issue(uint32_t sb, int buf, int k0, int tid,
    const bf16* A_hi, const bf16* A_lo, const bf16* B_hi, const bf16* B_lo, int K)
{
    const uint32_t base = sb + (uint32_t)buf * GS_STAGE;
    const bf16* srcs[4] = {A_hi, A_lo, B_hi, B_lo};
    const uint32_t offs[4] = {GS_A_HI, GS_A_LO, GS_B_HI, GS_B_LO};
#pragma unroll
    for (int m = 0; m < 4; m++) {
#pragma unroll
        for (int i = 0; i < 4; i++) {
            int c2 = tid + i * 256;           // 0..1023 (16B chunks)
            int row = c2 >> 3, cc = c2 & 7;   // 8 chunks per 64-col row
            cp16(base + offs[m] + row * 144 + cc * 16,
                 srcs[m] + (size_t)row * K + k0 + cc * 8);
        }
    }
}

template <int MODE>
__global__ __launch_bounds__(256, 1)
void gemm_mma_kernel(const bf16* __restrict__ Ahi, const bf16* __restrict__ Alo,
                     const bf16* __restrict__ Bhi, const bf16* __restrict__ Blo,
                     const float* __restrict__ bias, float* __restrict__ C,
                     bf16* __restrict__ qhi, bf16* __restrict__ qlo,
                     bf16* __restrict__ khi, bf16* __restrict__ klo,
                     bf16* __restrict__ vhi, bf16* __restrict__ vlo,
                     int K, int N)
{
    extern __shared__ __align__(16) char smem[];
    const uint32_t sb = smem_u32(smem);
    const int tid = threadIdx.x;
    const int wid = tid >> 5, lane = tid & 31;
    const int wm = wid & 3, wn = wid >> 2;        // 4 m-warps x 2 n-warps
    const int m0w = wm * 32, n0w = wn * 64;
    const int l8 = lane & 7, sel = lane >> 3, g = lane >> 2, q4 = lane & 3;
    const int bx = blockIdx.x, by = blockIdx.y;

    const bf16* a_hi = Ahi + (size_t)(by * 128) * K;
    const bf16* a_lo = Alo + (size_t)(by * 128) * K;
    const bf16* b_hi = Bhi + (size_t)(bx * 128) * K;
    const bf16* b_lo = Blo + (size_t)(bx * 128) * K;

    float acc[2][8][4];
#pragma unroll
    for (int t = 0; t < 2; t++)
#pragma unroll
        for (int j = 0; j < 8; j++)
#pragma unroll
            for (int r = 0; r < 4; r++) acc[t][j][r] = 0.0f;

    const int nst = K / 64;    // 16 stages

    // prologue: prefetch stages 0 and 1 (two groups in flight)
    gemm_issue(sb, 0, 0, tid, a_hi, a_lo, b_hi, b_lo, K);
    cp_commit();
    if (nst > 1) {
        gemm_issue(sb, 1, 64, tid, a_hi, a_lo, b_hi, b_lo, K);
        cp_commit();
    }

    for (int s = 0; s < nst; s++) {
        if (s + 1 < nst) cp_wait<1>();   // oldest group (stage s) done
        else             cp_wait<0>();
        __syncthreads();
        if (s + 2 < nst) {
            // buffer (s+2)%3 last read in iter s-1; barrier above protects it
            gemm_issue(sb, (s + 2) % 3, (s + 2) * 64, tid, a_hi, a_lo, b_hi, b_lo, K);
            cp_commit();
        }
        const uint32_t base = sb + (uint32_t)(s % 3) * GS_STAGE;
#pragma unroll
        for (int ks = 0; ks < 64; ks += 16) {
            uint32_t aH[2][4], aL[2][4];
#pragma unroll
            for (int t = 0; t < 2; t++) {
                uint32_t arow = m0w + t * 16 + l8 + (sel & 1) * 8;
                uint32_t acol = ks + (sel >> 1) * 8;
                ldsm_x4(aH[t], base + GS_A_HI + arow * 144 + acol * 2);
                ldsm_x4(aL[t], base + GS_A_LO + arow * 144 + acol * 2);
            }
            uint32_t bH[4][4], bL[4][4];
#pragma unroll
            for (int p = 0; p < 4; p++) {
                uint32_t brow = n0w + p * 16 + l8 + (sel >> 1) * 8;
                uint32_t bcol = ks + (sel & 1) * 8;
                ldsm_x4(bH[p], base + GS_B_HI + brow * 144 + bcol * 2);
                ldsm_x4(bL[p], base + GS_B_LO + brow * 144 + bcol * 2);
            }
#pragma unroll
            for (int t = 0; t < 2; t++)
#pragma unroll
                for (int j = 0; j < 8; j++) {
                    const uint32_t* bh_ = &bH[j >> 1][(j & 1) * 2];
                    const uint32_t* bl_ = &bL[j >> 1][(j & 1) * 2];
                    mma_bf16(acc[t][j], aH[t], bh_);
                    mma_bf16(acc[t][j], aH[t], bl_);
                    mma_bf16(acc[t][j], aL[t], bh_);
                }
        }
    }

    // epilogue
#pragma unroll
    for (int t = 0; t < 2; t++) {
        const int row = by * 128 + m0w + t * 16 + g;
#pragma unroll
        for (int j = 0; j < 8; j++) {
            const int col = bx * 128 + n0w + j * 8 + q4 * 2;
            const float b0 = bias[col], b1 = bias[col + 1];
            if (MODE == 0) {
                float2 v0 = make_float2(acc[t][j][0] + b0, acc[t][j][1] + b1);
                float2 v1 = make_float2(acc[t][j][2] + b0, acc[t][j][3] + b1);
                *(float2*)&C[(size_t)row * N + col] = v0;
                *(float2*)&C[(size_t)(row + 8) * N + col] = v1;
            } else {
                // fused gather+split: col -> (q|k|v, head, dim), row -> (b, s)
                const int seg = col >> 10;          // 0:q 1:k 2:v
                const int h   = (col & 1023) >> 6;
                const int d   = col & 63;
                bf16* dh = (seg == 0) ? qhi : (seg == 1) ? khi : vhi;
                bf16* dl = (seg == 0) ? qlo : (seg == 1) ? klo : vlo;
#pragma unroll
                for (int rr = 0; rr < 2; rr++) {
                    const int grow = row + rr * 8;
                    const size_t dst =
                        (((size_t)((grow >> 11) * PH + h)) * PS + (grow & 2047)) * PHD + d;
                    uint32_t lw;
                    uint32_t hw = split_pack(acc[t][j][rr * 2] + b0,
                                             acc[t][j][rr * 2 + 1] + b1, lw);
                    *(uint32_t*)&dh[dst] = hw;
                    *(uint32_t*)&dl[dst] = lw;
                }
            }
        }
    }
}

// ---------------------------------------------------------------------------
// FA2-style causal flash attention via mma.sync, split-bf16, fp32 softmax.
// CTA: 256 thr / 8 warps, q tile 128 (16 rows/warp), kv tiles of 64.
// Halved KV global traffic vs q-tile 64. 144B rows; KV double-buffered.
// smem 110.6KB -> 1 CTA/SM, 8 warps.
// ---------------------------------------------------------------------------
#define AS_Q_HI 0
#define AS_Q_LO 18432
#define AS_KV   36864
#define AS_KV_STAGE 36864
#define AS_K_LO 9216
#define AS_V_HI 18432
#define AS_V_LO 27648
#define ATT_SMEM (AS_KV + 2 * AS_KV_STAGE)   // 110592

__device__ __forceinline__ void attn_issue_kv(uint32_t sb, int stage, int kb, int tid,
    const bf16* kh, const bf16* kl, const bf16* vh, const bf16* vl)
{
    const uint32_t base = sb + AS_KV + (uint32_t)(stage & 1) * AS_KV_STAGE;
    const bf16* srcs[4] = {kh, kl, vh, vl};
#pragma unroll
    for (int m = 0; m < 4; m++) {
#pragma unroll
        for (int i = 0; i < 2; i++) {
            int c2 = tid + i * 256;          // 0..511 (64 rows x 8 chunks)
            int row = c2 >> 3, cc = c2 & 7;
            cp16(base + (uint32_t)m * 9216 + row * 144 + cc * 16,
                 srcs[m] + (size_t)(kb + row) * PHD + cc * 8);
        }
    }
}

__global__ __launch_bounds__(256, 1)
void flash_attn_mma_kernel(const bf16* __restrict__ qhi, const bf16* __restrict__ qlo,
                           const bf16* __restrict__ khi, const bf16* __restrict__ klo,
                           const bf16* __restrict__ vhi, const bf16* __restrict__ vlo,
                           bf16* __restrict__ ahi, bf16* __restrict__ alo)
{
    extern __shared__ __align__(16) char smem[];
    const uint32_t sb = smem_u32(smem);
    const int qt  = (int)gridDim.x - 1 - blockIdx.x;   // heavy tiles first
    const int bh  = blockIdx.y;
    const int tid = threadIdx.x;
    const int wid = tid >> 5, lane = tid & 31;         // wid 0..7
    const int l8 = lane & 7, sel = lane >> 3, g = lane >> 2, q4 = lane & 3;

    const bf16* qh = qhi + ((size_t)bh * PS + qt * 128) * PHD;
    const bf16* ql = qlo + ((size_t)bh * PS + qt * 128) * PHD;
    const bf16* kh = khi + (size_t)bh * PS * PHD;
    const bf16* kl = klo + (size_t)bh * PS * PHD;
    const bf16* vh = vhi + (size_t)bh * PS * PHD;
    const bf16* vl = vlo + (size_t)bh * PS * PHD;

    // prologue: Q tiles (2 x 128 rows x 8 chunks = 2048) + KV tile 0
#pragma unroll
    for (int i = 0; i < 8; i++) {
        int c2 = tid + i * 256;              // 0..2047
        int half = c2 >> 10;
        int w = c2 & 1023;
        int row = w >> 3, cc = w & 7;
        cp16(sb + (half ? AS_Q_LO : AS_Q_HI) + row * 144 + cc * 16,
             (half ? ql : qh) + (size_t)row * PHD + cc * 8);
    }
    attn_issue_kv(sb, 0, 0, tid, kh, kl, vh, vl);
    cp_commit();

    float o[8][4];
#pragma unroll
    for (int j = 0; j < 8; j++)
#pragma unroll
        for (int r = 0; r < 4; r++) o[j][r] = 0.0f;
    float m0 = -1e30f, m1 = -1e30f, l0 = 0.0f, l1 = 0.0f;
    uint32_t qa_h[4][4], qa_l[4][4];

    const int nkt = (qt + 1) * 2;
    for (int kt = 0; kt < nkt; kt++) {
        cp_wait<0>();
        __syncthreads();

        if (kt == 0) {
#pragma unroll
            for (int ks = 0; ks < 4; ks++) {
                uint32_t arow = wid * 16 + l8 + (sel & 1) * 8;   // rows 0..127
                uint32_t acol = ks * 16 + (sel >> 1) * 8;
                ldsm_x4(qa_h[ks], sb + AS_Q_HI + arow * 144 + acol * 2);
                ldsm_x4(qa_l[ks], sb + AS_Q_LO + arow * 144 + acol * 2);
            }
        }
        if (kt + 1 < nkt) {
            attn_issue_kv(sb, kt + 1, (kt + 1) * 64, tid, kh, kl, vh, vl);
            cp_commit();
        }

        const uint32_t kvb = sb + AS_KV + (uint32_t)(kt & 1) * AS_KV_STAGE;

        // S = Q K^T  (16 q rows x 64 keys per warp)
        float sc[8][4];
#pragma unroll
        for (int j = 0; j < 8; j++)
#pragma unroll
            for (int r = 0; r < 4; r++) sc[j][r] = 0.0f;
#pragma unroll
        for (int ks = 0; ks < 4; ks++) {
            uint32_t bH[4][4], bL[4][4];
#pragma unroll
            for (int p = 0; p < 4; p++) {
                uint32_t krow = p * 16 + l8 + (sel >> 1) * 8;
                uint32_t kcol = ks * 16 + (sel & 1) * 8;
                ldsm_x4(bH[p], kvb + krow * 144 + kcol * 2);
                ldsm_x4(bL[p], kvb + AS_K_LO + krow * 144 + kcol * 2);
            }
#pragma unroll
            for (int j = 0; j < 8; j++) {
                const uint32_t* bh_ = &bH[j >> 1][(j & 1) * 2];
                const uint32_t* bl_ = &bL[j >> 1][(j & 1) * 2];
                mma_bf16(sc[j], qa_h[ks], bh_);
                mma_bf16(sc[j], qa_h[ks], bl_);
                mma_bf16(sc[j], qa_l[ks], bh_);
            }
        }

        // scale + causal mask (any tile where keys can exceed this warp's rows)
        const int kb = kt * 64;
        const int r0g = qt * 128 + wid * 16 + g;
        const int r1g = r0g + 8;
        const bool diag = (kb + 63) > (qt * 128 + wid * 16);
#pragma unroll
        for (int j = 0; j < 8; j++) {
            const int c0 = kb + j * 8 + q4 * 2, c1 = c0 + 1;
            sc[j][0] *= 0.125f; sc[j][1] *= 0.125f;
            sc[j][2] *= 0.125f; sc[j][3] *= 0.125f;
            if (diag) {
                if (c0 > r0g) sc[j][0] = -1e9f;
                if (c1 > r0g) sc[j][1] = -1e9f;
                if (c0 > r1g) sc[j][2] = -1e9f;
                if (c1 > r1g) sc[j][3] = -1e9f;
            }
        }

        // online softmax (row groups: c0,c1 -> row g; c2,c3 -> row g+8)
        float tm0 = -1e30f, tm1 = -1e30f;
#pragma unroll
        for (int j = 0; j < 8; j++) {
            tm0 = fmaxf(tm0, fmaxf(sc[j][0], sc[j][1]));
            tm1 = fmaxf(tm1, fmaxf(sc[j][2], sc[j][3]));
        }
        tm0 = fmaxf(tm0, __shfl_xor_sync(0xffffffffu, tm0, 1));
        tm0 = fmaxf(tm0, __shfl_xor_sync(0xffffffffu, tm0, 2));
        tm1 = fmaxf(tm1, __shfl_xor_sync(0xffffffffu, tm1, 1));
        tm1 = fmaxf(tm1, __shfl_xor_sync(0xffffffffu, tm1, 2));
        const float mn0 = fmaxf(m0, tm0), mn1 = fmaxf(m1, tm1);
        const float al0 = __expf(m0 - mn0), al1 = __expf(m1 - mn1);
        m0 = mn0; m1 = mn1;
        float ls0 = 0.0f, ls1 = 0.0f;
#pragma unroll
        for (int j = 0; j < 8; j++) {
            sc[j][0] = __expf(sc[j][0] - mn0); ls0 += sc[j][0];
            sc[j][1] = __expf(sc[j][1] - mn0); ls0 += sc[j][1];
            sc[j][2] = __expf(sc[j][2] - mn1); ls1 += sc[j][2];
            sc[j][3] = __expf(sc[j][3] - mn1); ls1 += sc[j][3];
        }
        ls0 += __shfl_xor_sync(0xffffffffu, ls0, 1);
        ls0 += __shfl_xor_sync(0xffffffffu, ls0, 2);
        ls1 += __shfl_xor_sync(0xffffffffu, ls1, 1);
        ls1 += __shfl_xor_sync(0xffffffffu, ls1, 2);
        l0 = l0 * al0 + ls0;
        l1 = l1 * al1 + ls1;
#pragma unroll
        for (int j = 0; j < 8; j++) {
            o[j][0] *= al0; o[j][1] *= al0;
            o[j][2] *= al1; o[j][3] *= al1;
        }

        // O += P V   (P re-packed in-register as A fragments)
#pragma unroll
        for (int ks = 0; ks < 4; ks++) {
            uint32_t pa_h[4], pa_l[4];
            {
                const int j0 = ks * 2, j1 = ks * 2 + 1;
                pa_h[0] = split_pack(sc[j0][0], sc[j0][1], pa_l[0]);
                pa_h[1] = split_pack(sc[j0][2], sc[j0][3], pa_l[1]);
                pa_h[2] = split_pack(sc[j1][0], sc[j1][1], pa_l[2]);
                pa_h[3] = split_pack(sc[j1][2], sc[j1][3], pa_l[3]);
            }
            uint32_t vH[4][4], vL[4][4];
#pragma unroll
            for (int p = 0; p < 4; p++) {
                uint32_t vrow = ks * 16 + l8 + (sel & 1) * 8;
                uint32_t vcol = p * 16 + (sel >> 1) * 8;
                ldsm_x4_t(vH[p], kvb + AS_V_HI + vrow * 144 + vcol * 2);
                ldsm_x4_t(vL[p], kvb + AS_V_LO + vrow * 144 + vcol * 2);
            }
#pragma unroll
            for (int j = 0; j < 8; j++) {
                const uint32_t* bh_ = &vH[j >> 1][(j & 1) * 2];
                const uint32_t* bl_ = &vL[j >> 1][(j & 1) * 2];
                mma_bf16(o[j], pa_h, bh_);
                mma_bf16(o[j], pa_h, bl_);
                mma_bf16(o[j], pa_l, bh_);
            }
        }
    }

    // epilogue: normalize, split hi/lo, store (merged-head layout)
    const float inv0 = 1.0f / l0, inv1 = 1.0f / l1;
    const int b = bh >> 4, h = bh & 15;
    const int r0 = b * PS + qt * 128 + wid * 16 + g;
#pragma unroll
    for (int j = 0; j < 8; j++) {
        const int col = h * PHD + j * 8 + q4 * 2;
        uint32_t lw;
        uint32_t hw = split_pack(o[j][0] * inv0, o[j][1] * inv0, lw);
        *(uint32_t*)&ahi[(size_t)r0 * PD + col] = hw;
        *(uint32_t*)&alo[(size_t)r0 * PD + col] = lw;
        hw = split_pack(o[j][2] * inv1, o[j][3] * inv1, lw);
        *(uint32_t*)&ahi[(size_t)(r0 + 8) * PD + col] = hw;
        *(uint32_t*)&alo[(size_t)(r0 + 8) * PD + col] = lw;
    }
}

// ---------------------------------------------------------------------------
// Launch
// ---------------------------------------------------------------------------
extern "C" void kernel_launch(void* const* d_in, const int* in_sizes, int n_in,
                              void* d_out, int out_size)
{
    const float* x     = (const float*)d_in[0];
    const float* Wqkv  = (const float*)d_in[1];
    const float* bqkv  = (const float*)d_in[2];
    const float* Wout  = (const float*)d_in[3];
    const float* bout  = (const float*)d_in[4];
    float*       out   = (float*)d_out;

    bf16 *xhi, *xlo, *wqThi, *wqTlo, *woThi, *woTlo;
    bf16 *qhi, *qlo, *khi, *klo, *vhi, *vlo, *ahi, *alo;
    cudaGetSymbolAddress((void**)&xhi,   g_xhi);
    cudaGetSymbolAddress((void**)&xlo,   g_xlo);
    cudaGetSymbolAddress((void**)&wqThi, g_wqT_hi);
    cudaGetSymbolAddress((void**)&wqTlo, g_wqT_lo);
    cudaGetSymbolAddress((void**)&woThi, g_woT_hi);
    cudaGetSymbolAddress((void**)&woTlo, g_woT_lo);
    cudaGetSymbolAddress((void**)&qhi,   g_qhi);
    cudaGetSymbolAddress((void**)&qlo,   g_qlo);
    cudaGetSymbolAddress((void**)&khi,   g_khi);
    cudaGetSymbolAddress((void**)&klo,   g_klo);
    cudaGetSymbolAddress((void**)&vhi,   g_vhi);
    cudaGetSymbolAddress((void**)&vlo,   g_vlo);
    cudaGetSymbolAddress((void**)&ahi,   g_ahi);
    cudaGetSymbolAddress((void**)&alo,   g_alo);

    cudaFuncSetAttribute(gemm_mma_kernel<0>, cudaFuncAttributeMaxDynamicSharedMemorySize, GEMM_SMEM);
    cudaFuncSetAttribute(gemm_mma_kernel<1>, cudaFuncAttributeMaxDynamicSharedMemorySize, GEMM_SMEM);
    cudaFuncSetAttribute(flash_attn_mma_kernel, cudaFuncAttributeMaxDynamicSharedMemorySize, ATT_SMEM);

    // pre-passes
    {
        int n4 = (M_ROWS * PD) / 4;
        convert_x_kernel<<<(n4 + 255) / 256, 256>>>(x, xhi, xlo, n4);
    }
    {
        dim3 g(QKV_N / 32, PD / 32), blk(32, 8);
        transpose_split_kernel<<<g, blk>>>(Wqkv, wqThi, wqTlo, PD, QKV_N);
    }
    {
        dim3 g(PD / 32, PD / 32), blk(32, 8);
        transpose_split_kernel<<<g, blk>>>(Wout, woThi, woTlo, PD, PD);
    }
    // 1) QKV projection with fused gather/split epilogue
    {
        dim3 grid(QKV_N / 128, M_ROWS / 128);
        gemm_mma_kernel<1><<<grid, 256, GEMM_SMEM>>>(
            xhi, xlo, wqThi, wqTlo, bqkv, nullptr,
            qhi, qlo, khi, klo, vhi, vlo, PD, QKV_N);
    }
    // 2) causal flash attention (q tile 128, 8 warps)
    {
        dim3 grid(PS / 128, PB * PH);
        flash_attn_mma_kernel<<<grid, 256, ATT_SMEM>>>(qhi, qlo, khi, klo, vhi, vlo, ahi, alo);
    }
    // 3) output projection (fp32 epilogue)
    {
        dim3 grid(PD / 128, M_ROWS / 128);
        gemm_mma_kernel<0><<<grid, 256, GEMM_SMEM>>>(
            ahi, alo, woThi, woTlo, bout, out,
            nullptr, nullptr, nullptr, nullptr, nullptr, nullptr, PD, PD);
    }
}